// round 17
// baseline (speedup 1.0000x reference)
#include <cuda_runtime.h>
#include <cstdint>

#define BSZ 8192
#define DIM 128
#define BM 64
#define BN 128
#define NBLK (BSZ / BM)     // 128
#define NTILES (BSZ / BN)   // 64
#define SA 68               // As stride (words)
#define SB 132              // Bs stride (words)

// scratch (device globals — no allocation; R1-proven minimal set)
__device__ float g_xn[BSZ * DIM];
__device__ int   g_lab[BSZ];
__device__ int   g_n1;
__device__ float g_partials[NBLK];

// ---------------------------------------------------------------------------
// Kernel 1: count class-1 labels (verbatim R1)
// ---------------------------------------------------------------------------
__global__ void count_kernel(const long long* __restrict__ label) {
    __shared__ int sh[256];
    int tid = threadIdx.x;
    int acc = 0;
    for (int i = tid; i < BSZ; i += 256) acc += (int)label[i];
    sh[tid] = acc;
    __syncthreads();
    for (int s = 128; s > 0; s >>= 1) {
        if (tid < s) sh[tid] += sh[tid + s];
        __syncthreads();
    }
    if (tid == 0) g_n1 = sh[0];
}

// ---------------------------------------------------------------------------
// Kernel 2: L2-normalize rows (verbatim R1)
// ---------------------------------------------------------------------------
__global__ void normalize_kernel(const float* __restrict__ data,
                                 const long long* __restrict__ label) {
    int warp = threadIdx.x >> 5;
    int lane = threadIdx.x & 31;
    int row  = blockIdx.x * 8 + warp;

    float4 v = ((const float4*)(data + (size_t)row * DIM))[lane];
    float ss = v.x * v.x + v.y * v.y + v.z * v.z + v.w * v.w;
#pragma unroll
    for (int o = 16; o; o >>= 1) ss += __shfl_xor_sync(0xffffffffu, ss, o);

    float n   = fmaxf(sqrtf(ss), 1e-12f);
    float inv = 1.0f / n;
    float4 o4 = make_float4(v.x * inv, v.y * inv, v.z * inv, v.w * inv);
    ((float4*)(g_xn + (size_t)row * DIM))[lane] = o4;

    if (lane == 0) g_lab[row] = (int)label[row];
}

// ---------------------------------------------------------------------------
// Kernel 3: fused GEMM + streaming row reductions. R14 structure; delta:
// double-buffered B tile with register-staged prefetch (LDG.128 issued before
// the FMA block, STS after it) and ONE barrier per chunk. Scalar FFMA only.
// ---------------------------------------------------------------------------
__global__ __launch_bounds__(256, 1)
void main_kernel(const float* __restrict__ scale_ptr) {
    extern __shared__ float sm[];
    float* As   = sm;                          // [DIM][SA], A^T
    float* Bs0  = sm + DIM * SA;               // [DIM][SB], B^T buf 0
    float* Bs1  = Bs0 + DIM * SB;              // [DIM][SB], B^T buf 1
    int*   labB = (int*)(Bs1 + DIM * SB);      // [2][BN]

    const int tid = threadIdx.x;
    const int tx  = tid & 15;                  // column group
    const int ty  = tid >> 4;                  // row group (rows ty*4..ty*4+3)
    const int rowbase = blockIdx.x * BM;
    const float s = expf(*scale_ptr);

    // Load A tile once, transposed (global coalesced) — R1 pattern
    for (int i = tid; i < BM * DIM; i += 256) {
        int r = i >> 7, k = i & (DIM - 1);
        As[k * SA + r] = g_xn[(size_t)(rowbase + r) * DIM + k];
    }

    // Prologue: fill B buf0 directly (exposed once)
    for (int i = tid; i < BN * DIM; i += 256) {
        int r = i >> 7, k = i & (DIM - 1);
        Bs0[k * SB + r] = g_xn[(size_t)r * DIM + k];
    }
    if (tid < BN) labB[tid] = g_lab[tid];
    __syncthreads();

    int labR[4];
#pragma unroll
    for (int j = 0; j < 4; j++) labR[j] = g_lab[rowbase + ty * 4 + j];

    float accZ[4] = {0}, accT[4] = {0}, accS[4] = {0}, accE[4] = {0}, accQ[4] = {0};

    for (int t = 0; t < NTILES; t++) {
        const float* Bs = (t & 1) ? Bs1 : Bs0;
        const int*   lb = labB + (t & 1) * BN;

        // ---- stage next chunk into registers (LDG.128, no dependents yet) ----
        float4 stg[16];
        if (t + 1 < NTILES) {
            const float* gB = g_xn + (size_t)(t + 1) * BN * DIM;
#pragma unroll
            for (int n = 0; n < 16; n++)
                stg[n] = *(const float4*)(gB + (size_t)(tid + n * 256) * 4);
        }

        // ---- GEMM: 4x8 per thread (R14 verbatim) ----
        float acc[4][8];
#pragma unroll
        for (int j = 0; j < 4; j++)
#pragma unroll
            for (int c = 0; c < 8; c++) acc[j][c] = 0.f;

#pragma unroll 8
        for (int k = 0; k < DIM; k++) {
            float4 a4  = *(const float4*)&As[k * SA + ty * 4];
            float4 b4a = *(const float4*)&Bs[k * SB + tx * 4];
            float4 b4b = *(const float4*)&Bs[k * SB + 64 + tx * 4];
            float av[4] = {a4.x, a4.y, a4.z, a4.w};
            float bv[8] = {b4a.x, b4a.y, b4a.z, b4a.w, b4b.x, b4b.y, b4b.z, b4b.w};
#pragma unroll
            for (int j = 0; j < 4; j++)
#pragma unroll
                for (int c = 0; c < 8; c++)
                    acc[j][c] = fmaf(av[j], bv[c], acc[j][c]);
        }

        // ---- fused epilogue (R14 verbatim) ----
        int lc[8];
#pragma unroll
        for (int c = 0; c < 8; c++) lc[c] = lb[(c >> 2) * 64 + tx * 4 + (c & 3)];

#pragma unroll
        for (int j = 0; j < 4; j++) {
#pragma unroll
            for (int c = 0; c < 8; c++) {
                float l = s * acc[j][c];
                float e = __expf(l - s);
                accZ[j] += e;
                accT[j] = fmaf(e, l, accT[j]);
                accS[j] += l;
                if (lc[c] == labR[j]) { accE[j] += e; accQ[j] += l; }
            }
        }

        // ---- drain staged registers into the other buffer ----
        if (t + 1 < NTILES) {
            float* Bn = (t & 1) ? Bs0 : Bs1;
#pragma unroll
            for (int n = 0; n < 16; n++) {
                int i = tid + n * 256;            // float4 index
                int r = i >> 5, k4 = (i & 31) * 4;
                Bn[(k4 + 0) * SB + r] = stg[n].x;
                Bn[(k4 + 1) * SB + r] = stg[n].y;
                Bn[(k4 + 2) * SB + r] = stg[n].z;
                Bn[(k4 + 3) * SB + r] = stg[n].w;
            }
            if (tid < BN) labB[(1 - (t & 1)) * BN + tid] = g_lab[(t + 1) * BN + tid];
        }
        __syncthreads();                          // ONE barrier per chunk
    }

    // ---- reduce across the 16-thread column group (R1 pattern) ----
#pragma unroll
    for (int j = 0; j < 4; j++) {
#pragma unroll
        for (int o = 8; o; o >>= 1) {
            accZ[j] += __shfl_xor_sync(0xffffffffu, accZ[j], o);
            accT[j] += __shfl_xor_sync(0xffffffffu, accT[j], o);
            accS[j] += __shfl_xor_sync(0xffffffffu, accS[j], o);
            accE[j] += __shfl_xor_sync(0xffffffffu, accE[j], o);
            accQ[j] += __shfl_xor_sync(0xffffffffu, accQ[j], o);
        }
    }

    __shared__ float red[16];
    if (tx == 0) {
        const int n1 = g_n1;
        double total = 0.0;
#pragma unroll
        for (int j = 0; j < 4; j++) {
            int ci = labR[j] ? n1 : (BSZ - n1);
            double cd  = (double)ci;
            double ic  = 1.0 / cd;
            double eic = exp(ic);
            double Dd  = cd * eic + (double)(BSZ - ci);
            double qd  = 1.0 / Dd;
            double qs  = eic / Dd;
            double Z   = (double)accZ[j];
            double v   = qs + (double)accT[j] / Z
                       - qd * (double)accS[j]
                       - (qs - qd) * (double)accQ[j]
                       - ((double)accE[j] / Z) * ic;
            total += v;
        }
        red[ty] = (float)total;
    }
    __syncthreads();
    if (tid == 0) {
        float sum = 0.f;
#pragma unroll
        for (int i = 0; i < 16; i++) sum += red[i];
        g_partials[blockIdx.x] = sum;
    }
}

// ---------------------------------------------------------------------------
// Kernel 4: deterministic final reduction (verbatim R1)
// ---------------------------------------------------------------------------
__global__ void final_kernel(float* __restrict__ out) {
    __shared__ float sh[128];
    int tid = threadIdx.x;
    sh[tid] = g_partials[tid];
    __syncthreads();
    for (int s = 64; s > 0; s >>= 1) {
        if (tid < s) sh[tid] += sh[tid + s];
        __syncthreads();
    }
    if (tid == 0) out[0] = sh[0] / (2.0f * (float)BSZ);
}

// ---------------------------------------------------------------------------
extern "C" void kernel_launch(void* const* d_in, const int* in_sizes, int n_in,
                              void* d_out, int out_size) {
    const float*     data  = (const float*)d_in[0];
    const float*     scale = (const float*)d_in[1];
    const long long* label = (const long long*)d_in[2];
    float*           out   = (float*)d_out;

    size_t smem = (size_t)(DIM * SA + 2 * DIM * SB) * sizeof(float)
                + 2 * BN * sizeof(int);            // 171,008 B
    cudaFuncSetAttribute(main_kernel, cudaFuncAttributeMaxDynamicSharedMemorySize,
                         (int)smem);

    count_kernel<<<1, 256>>>(label);
    normalize_kernel<<<BSZ / 8, 256>>>(data, label);
    main_kernel<<<NBLK, 256, smem>>>(scale);
    final_kernel<<<1, 128>>>(out);
}